// round 1
// baseline (speedup 1.0000x reference)
#include <cuda_runtime.h>
#include <math.h>

#define NMAX 100000
#define ACC_W 16   // [coeff, edge_sca*coeff (6), edge_vec*coeff (9)]

__device__ float g_acc[NMAX * ACC_W];

// ---------------------------------------------------------------------------
// Zero the per-node accumulator
// ---------------------------------------------------------------------------
__global__ void zero_kernel(int total) {
    for (int i = blockIdx.x * blockDim.x + threadIdx.x; i < total;
         i += gridDim.x * blockDim.x)
        g_acc[i] = 0.0f;
}

// ---------------------------------------------------------------------------
// Edge phase: 16 lanes per edge, each lane scatters one accumulator slot.
//   slot 0      : coeff
//   slots 1..6  : edge_sca[c] * coeff
//   slots 7..15 : edge_vec[c][i] * coeff
// ---------------------------------------------------------------------------
__global__ void edge_kernel(const float* __restrict__ edge_sca,
                            const float* __restrict__ edge_vec,
                            const float* __restrict__ gds,
                            const int*   __restrict__ src_idx,
                            int E) {
    long long tid = (long long)blockIdx.x * blockDim.x + threadIdx.x;
    int e = (int)(tid >> 4);
    int j = (int)(tid & 15);
    if (e >= E) return;

    float dist = __ldg(gds + e);                 // broadcast within 16-lane group
    if (dist > 10.0f || dist < 0.0f) return;     // coeff == 0 -> no contribution
    float coeff = 0.5f * (__cosf(dist * 0.31415926535f) + 1.0f);

    int src = __ldg(src_idx + e);                // broadcast load

    float v;
    if (j == 0)      v = coeff;
    else if (j < 7)  v = __ldg(edge_sca + e * 6 + (j - 1)) * coeff;
    else             v = __ldg(edge_vec + e * 9 + (j - 7)) * coeff;

    atomicAdd(g_acc + src * ACC_W + j, v);
}

// ---------------------------------------------------------------------------
// Node phase: projections + GVPerceptronVN + VNLeakyReLU, 1 thread / node.
// Weights staged in shared memory (warp-uniform LDS broadcast).
// ---------------------------------------------------------------------------
// shared layout offsets (floats)
#define O_NSS   0      // 4x16
#define O_BNSS  64     // 16
#define O_ESS   80     // 6x16
#define O_BESS  176    // 16
#define O_NSV   192    // 4x16
#define O_BNSV  256    // 16
#define O_ESV   272    // 6x16
#define O_BESV  368    // 16
#define O_NVV   384    // 3x16
#define O_EVV   432    // 3x16
#define O_LV    480    // 16x16
#define O_LV2   736    // 16x16
#define O_LS    992    // 32x16
#define O_GATE  1504   // 16x16
#define O_BGATE 1760   // 16
#define O_DIR   1776   // 16x16
#define SW_TOT  2032

__global__ void __launch_bounds__(128)
node_kernel(const float* __restrict__ node_sca,
            const float* __restrict__ node_vec,
            const float* __restrict__ W_nss, const float* __restrict__ b_nss,
            const float* __restrict__ W_ess, const float* __restrict__ b_ess,
            const float* __restrict__ W_nsv, const float* __restrict__ b_nsv,
            const float* __restrict__ W_esv, const float* __restrict__ b_esv,
            const float* __restrict__ W_nvv, const float* __restrict__ W_evv,
            const float* __restrict__ W_lv,  const float* __restrict__ W_lv2,
            const float* __restrict__ W_ls,  const float* __restrict__ W_gate,
            const float* __restrict__ b_gate,const float* __restrict__ W_dir,
            float* __restrict__ out, int N) {
    __shared__ float sW[SW_TOT];
    {
        const float* srcs[16] = {W_nss, b_nss, W_ess, b_ess, W_nsv, b_nsv,
                                 W_esv, b_esv, W_nvv, W_evv, W_lv, W_lv2,
                                 W_ls, W_gate, b_gate, W_dir};
        const int offs[17] = {O_NSS, O_BNSS, O_ESS, O_BESS, O_NSV, O_BNSV,
                              O_ESV, O_BESV, O_NVV, O_EVV, O_LV, O_LV2,
                              O_LS, O_GATE, O_BGATE, O_DIR, SW_TOT};
        for (int a = 0; a < 16; a++) {
            int cnt = offs[a + 1] - offs[a];
            for (int i = threadIdx.x; i < cnt; i += blockDim.x)
                sW[offs[a] + i] = srcs[a][i];
        }
    }
    __syncthreads();

    int n = blockIdx.x * blockDim.x + threadIdx.x;
    if (n >= N) return;

    // ---- per-node inputs + edge accumulators ----
    float ns[4];
#pragma unroll
    for (int c = 0; c < 4; c++) ns[c] = node_sca[n * 4 + c];
    float nv[3][3];
#pragma unroll
    for (int c = 0; c < 3; c++)
#pragma unroll
        for (int i = 0; i < 3; i++) nv[c][i] = node_vec[n * 9 + c * 3 + i];

    float Cs = g_acc[n * ACC_W + 0];
    float Es[6];
#pragma unroll
    for (int c = 0; c < 6; c++) Es[c] = g_acc[n * ACC_W + 1 + c];
    float Ev[3][3];
#pragma unroll
    for (int c = 0; c < 3; c++)
#pragma unroll
        for (int i = 0; i < 3; i++) Ev[c][i] = g_acc[n * ACC_W + 7 + c * 3 + i];

    // ---- fused message aggregation (factored form) ----
    float aggr_sca[16];
    float aggr_vec[16][3];
#pragma unroll
    for (int o = 0; o < 16; o++) {
        float nss = sW[O_BNSS + o];
        float nsv = sW[O_BNSV + o];
#pragma unroll
        for (int c = 0; c < 4; c++) {
            nss += ns[c] * sW[O_NSS + c * 16 + o];
            nsv += ns[c] * sW[O_NSV + c * 16 + o];
        }
        float ess = sW[O_BESS + o] * Cs;
        float esv = sW[O_BESV + o] * Cs;
#pragma unroll
        for (int c = 0; c < 6; c++) {
            ess += Es[c] * sW[O_ESS + c * 16 + o];
            esv += Es[c] * sW[O_ESV + c * 16 + o];
        }
        aggr_sca[o] = nss * ess;
#pragma unroll
        for (int i = 0; i < 3; i++) {
            float nvv = 0.0f, evv = 0.0f;
#pragma unroll
            for (int c = 0; c < 3; c++) {
                nvv += nv[c][i] * sW[O_NVV + c * 16 + o];
                evv += Ev[c][i] * sW[O_EVV + c * 16 + o];
            }
            aggr_vec[o][i] = nvv * esv + nsv * evv;
        }
    }

    // ---- GVLinear ----
    float v_inter[16][3];
    float v_norm[16];
#pragma unroll
    for (int o = 0; o < 16; o++) {
        float s0 = 0.0f, s1 = 0.0f, s2 = 0.0f;
#pragma unroll
        for (int c = 0; c < 16; c++) {
            float w = sW[O_LV + c * 16 + o];
            s0 += aggr_vec[c][0] * w;
            s1 += aggr_vec[c][1] * w;
            s2 += aggr_vec[c][2] * w;
        }
        v_inter[o][0] = s0; v_inter[o][1] = s1; v_inter[o][2] = s2;
        v_norm[o] = sqrtf(s0 * s0 + s1 * s1 + s2 * s2);
    }

    float osca[16];
#pragma unroll
    for (int o = 0; o < 16; o++) {
        float s = 0.0f;
#pragma unroll
        for (int c = 0; c < 16; c++) {
            s += v_norm[c] * sW[O_LS + c * 16 + o];
            s += aggr_sca[c] * sW[O_LS + (c + 16) * 16 + o];
        }
        osca[o] = s;
    }

    float gate[16];
#pragma unroll
    for (int o = 0; o < 16; o++) {
        float g = sW[O_BGATE + o];
#pragma unroll
        for (int c = 0; c < 16; c++) g += osca[c] * sW[O_GATE + c * 16 + o];
        gate[o] = 1.0f / (1.0f + __expf(-g));
    }

    float ovec[16][3];
#pragma unroll
    for (int o = 0; o < 16; o++) {
        float s0 = 0.0f, s1 = 0.0f, s2 = 0.0f;
#pragma unroll
        for (int c = 0; c < 16; c++) {
            float w = sW[O_LV2 + c * 16 + o];
            s0 += v_inter[c][0] * w;
            s1 += v_inter[c][1] * w;
            s2 += v_inter[c][2] * w;
        }
        ovec[o][0] = s0 * gate[o];
        ovec[o][1] = s1 * gate[o];
        ovec[o][2] = s2 * gate[o];
    }

    // ---- VNLeakyReLU on vectors ----
    float res[48];
#pragma unroll
    for (int o = 0; o < 16; o++) {
        float d0 = 0.0f, d1 = 0.0f, d2 = 0.0f;
#pragma unroll
        for (int c = 0; c < 16; c++) {
            float w = sW[O_DIR + c * 16 + o];
            d0 += ovec[c][0] * w;
            d1 += ovec[c][1] * w;
            d2 += ovec[c][2] * w;
        }
        float v0 = ovec[o][0], v1 = ovec[o][1], v2 = ovec[o][2];
        float dot = v0 * d0 + v1 * d1 + v2 * d2;
        float r0 = v0, r1 = v1, r2 = v2;
        if (dot < 0.0f) {
            float k = 0.8f * dot / (d0 * d0 + d1 * d1 + d2 * d2 + 1e-6f);
            r0 = v0 - k * d0;
            r1 = v1 - k * d1;
            r2 = v2 - k * d2;
        }
        res[o * 3 + 0] = r0; res[o * 3 + 1] = r1; res[o * 3 + 2] = r2;
    }

    // ---- writes (vectorized) ----
    float* out_sca = out;
    float* out_vec = out + (size_t)N * 16;

    float4* dv = (float4*)(out_vec + (size_t)n * 48);
#pragma unroll
    for (int q = 0; q < 12; q++)
        dv[q] = make_float4(res[q * 4 + 0], res[q * 4 + 1],
                            res[q * 4 + 2], res[q * 4 + 3]);

    float ssca[16];
#pragma unroll
    for (int o = 0; o < 16; o++) {
        float s = osca[o];
        ssca[o] = (s >= 0.0f) ? s : 0.01f * s;
    }
    float4* ds = (float4*)(out_sca + (size_t)n * 16);
#pragma unroll
    for (int q = 0; q < 4; q++)
        ds[q] = make_float4(ssca[q * 4 + 0], ssca[q * 4 + 1],
                            ssca[q * 4 + 2], ssca[q * 4 + 3]);
}

// ---------------------------------------------------------------------------
extern "C" void kernel_launch(void* const* d_in, const int* in_sizes, int n_in,
                              void* d_out, int out_size) {
    const float* node_sca = (const float*)d_in[0];
    const float* node_vec = (const float*)d_in[1];
    const float* edge_sca = (const float*)d_in[2];
    const float* edge_vec = (const float*)d_in[3];
    const float* gds      = (const float*)d_in[4];
    const int*   ei       = (const int*)d_in[5];   // [2,E]; row 0 = src
    const float* W_nss  = (const float*)d_in[6];
    const float* b_nss  = (const float*)d_in[7];
    const float* W_ess  = (const float*)d_in[8];
    const float* b_ess  = (const float*)d_in[9];
    const float* W_nsv  = (const float*)d_in[10];
    const float* b_nsv  = (const float*)d_in[11];
    const float* W_esv  = (const float*)d_in[12];
    const float* b_esv  = (const float*)d_in[13];
    const float* W_nvv  = (const float*)d_in[14];
    const float* W_evv  = (const float*)d_in[15];
    const float* W_lv   = (const float*)d_in[16];
    const float* W_lv2  = (const float*)d_in[17];
    const float* W_ls   = (const float*)d_in[18];
    const float* W_gate = (const float*)d_in[19];
    const float* b_gate = (const float*)d_in[20];
    const float* W_dir  = (const float*)d_in[21];

    int N = in_sizes[0] / 4;
    int E = in_sizes[4];

    zero_kernel<<<256, 256>>>(N * ACC_W);

    long long ethreads = (long long)E * 16;
    int eblocks = (int)((ethreads + 255) / 256);
    edge_kernel<<<eblocks, 256>>>(edge_sca, edge_vec, gds, ei, E);

    int nblocks = (N + 127) / 128;
    node_kernel<<<nblocks, 128>>>(node_sca, node_vec,
                                  W_nss, b_nss, W_ess, b_ess,
                                  W_nsv, b_nsv, W_esv, b_esv,
                                  W_nvv, W_evv, W_lv, W_lv2,
                                  W_ls, W_gate, b_gate, W_dir,
                                  (float*)d_out, N);
}

// round 2
// speedup vs baseline: 1.3202x; 1.3202x over previous
#include <cuda_runtime.h>
#include <math.h>

#define NMAX 100000
#define ACC_W 16   // [coeff, edge_sca*coeff (6), edge_vec*coeff (9)]

__device__ __align__(16) float g_acc[NMAX * ACC_W];

// ---------------------------------------------------------------------------
// Zero the per-node accumulator (float4 stores)
// ---------------------------------------------------------------------------
__global__ void zero_kernel(int total4) {
    int i = blockIdx.x * blockDim.x + threadIdx.x;
    if (i < total4)
        ((float4*)g_acc)[i] = make_float4(0.f, 0.f, 0.f, 0.f);
}

// ---------------------------------------------------------------------------
// Edge phase: ONE thread per edge, 4 x red.global.add.v4.f32
//   slot 0      : coeff
//   slots 1..6  : edge_sca[c] * coeff
//   slots 7..15 : edge_vec[c][i] * coeff
// ---------------------------------------------------------------------------
__device__ __forceinline__ void red_v4(float* p, float a, float b, float c, float d) {
    asm volatile("red.global.add.v4.f32 [%0], {%1,%2,%3,%4};"
                 :: "l"(p), "f"(a), "f"(b), "f"(c), "f"(d) : "memory");
}

__global__ void __launch_bounds__(256)
edge_kernel(const float* __restrict__ edge_sca,
            const float* __restrict__ edge_vec,
            const float* __restrict__ gds,
            const int*   __restrict__ src_idx,
            int E) {
    int e = blockIdx.x * blockDim.x + threadIdx.x;
    if (e >= E) return;

    float dist = __ldg(gds + e);
    if (dist > 10.0f || dist < 0.0f) return;     // coeff == 0 -> no contribution
    float coeff = 0.5f * (__cosf(dist * 0.31415926535f) + 1.0f);

    int src = __ldg(src_idx + e);

    float es[6];
#pragma unroll
    for (int c = 0; c < 6; c++) es[c] = __ldg(edge_sca + e * 6 + c) * coeff;
    float ev[9];
#pragma unroll
    for (int c = 0; c < 9; c++) ev[c] = __ldg(edge_vec + e * 9 + c) * coeff;

    float* base = g_acc + (size_t)src * ACC_W;
    red_v4(base + 0,  coeff, es[0], es[1], es[2]);
    red_v4(base + 4,  es[3], es[4], es[5], ev[0]);
    red_v4(base + 8,  ev[1], ev[2], ev[3], ev[4]);
    red_v4(base + 12, ev[5], ev[6], ev[7], ev[8]);
}

// ---------------------------------------------------------------------------
// Node phase: projections + GVPerceptronVN + VNLeakyReLU, 1 thread / node.
// Weights staged in shared memory (warp-uniform LDS broadcast).
// ---------------------------------------------------------------------------
// shared layout offsets (floats)
#define O_NSS   0      // 4x16
#define O_BNSS  64     // 16
#define O_ESS   80     // 6x16
#define O_BESS  176    // 16
#define O_NSV   192    // 4x16
#define O_BNSV  256    // 16
#define O_ESV   272    // 6x16
#define O_BESV  368    // 16
#define O_NVV   384    // 3x16
#define O_EVV   432    // 3x16
#define O_LV    480    // 16x16
#define O_LV2   736    // 16x16
#define O_LS    992    // 32x16
#define O_GATE  1504   // 16x16
#define O_BGATE 1760   // 16
#define O_DIR   1776   // 16x16
#define SW_TOT  2032

__global__ void __launch_bounds__(128)
node_kernel(const float* __restrict__ node_sca,
            const float* __restrict__ node_vec,
            const float* __restrict__ W_nss, const float* __restrict__ b_nss,
            const float* __restrict__ W_ess, const float* __restrict__ b_ess,
            const float* __restrict__ W_nsv, const float* __restrict__ b_nsv,
            const float* __restrict__ W_esv, const float* __restrict__ b_esv,
            const float* __restrict__ W_nvv, const float* __restrict__ W_evv,
            const float* __restrict__ W_lv,  const float* __restrict__ W_lv2,
            const float* __restrict__ W_ls,  const float* __restrict__ W_gate,
            const float* __restrict__ b_gate,const float* __restrict__ W_dir,
            float* __restrict__ out, int N) {
    __shared__ float sW[SW_TOT];
    {
        const float* srcs[16] = {W_nss, b_nss, W_ess, b_ess, W_nsv, b_nsv,
                                 W_esv, b_esv, W_nvv, W_evv, W_lv, W_lv2,
                                 W_ls, W_gate, b_gate, W_dir};
        const int offs[17] = {O_NSS, O_BNSS, O_ESS, O_BESS, O_NSV, O_BNSV,
                              O_ESV, O_BESV, O_NVV, O_EVV, O_LV, O_LV2,
                              O_LS, O_GATE, O_BGATE, O_DIR, SW_TOT};
        for (int a = 0; a < 16; a++) {
            int cnt = offs[a + 1] - offs[a];
            for (int i = threadIdx.x; i < cnt; i += blockDim.x)
                sW[offs[a] + i] = srcs[a][i];
        }
    }
    __syncthreads();

    int n = blockIdx.x * blockDim.x + threadIdx.x;
    if (n >= N) return;

    // ---- per-node inputs + edge accumulators ----
    float ns[4];
#pragma unroll
    for (int c = 0; c < 4; c++) ns[c] = node_sca[n * 4 + c];
    float nv[3][3];
#pragma unroll
    for (int c = 0; c < 3; c++)
#pragma unroll
        for (int i = 0; i < 3; i++) nv[c][i] = node_vec[n * 9 + c * 3 + i];

    float Cs = g_acc[n * ACC_W + 0];
    float Es[6];
#pragma unroll
    for (int c = 0; c < 6; c++) Es[c] = g_acc[n * ACC_W + 1 + c];
    float Ev[3][3];
#pragma unroll
    for (int c = 0; c < 3; c++)
#pragma unroll
        for (int i = 0; i < 3; i++) Ev[c][i] = g_acc[n * ACC_W + 7 + c * 3 + i];

    // ---- fused message aggregation (factored form) ----
    float aggr_sca[16];
    float aggr_vec[16][3];
#pragma unroll
    for (int o = 0; o < 16; o++) {
        float nss = sW[O_BNSS + o];
        float nsv = sW[O_BNSV + o];
#pragma unroll
        for (int c = 0; c < 4; c++) {
            nss += ns[c] * sW[O_NSS + c * 16 + o];
            nsv += ns[c] * sW[O_NSV + c * 16 + o];
        }
        float ess = sW[O_BESS + o] * Cs;
        float esv = sW[O_BESV + o] * Cs;
#pragma unroll
        for (int c = 0; c < 6; c++) {
            ess += Es[c] * sW[O_ESS + c * 16 + o];
            esv += Es[c] * sW[O_ESV + c * 16 + o];
        }
        aggr_sca[o] = nss * ess;
#pragma unroll
        for (int i = 0; i < 3; i++) {
            float nvv = 0.0f, evv = 0.0f;
#pragma unroll
            for (int c = 0; c < 3; c++) {
                nvv += nv[c][i] * sW[O_NVV + c * 16 + o];
                evv += Ev[c][i] * sW[O_EVV + c * 16 + o];
            }
            aggr_vec[o][i] = nvv * esv + nsv * evv;
        }
    }

    // ---- GVLinear ----
    float v_inter[16][3];
    float v_norm[16];
#pragma unroll
    for (int o = 0; o < 16; o++) {
        float s0 = 0.0f, s1 = 0.0f, s2 = 0.0f;
#pragma unroll
        for (int c = 0; c < 16; c++) {
            float w = sW[O_LV + c * 16 + o];
            s0 += aggr_vec[c][0] * w;
            s1 += aggr_vec[c][1] * w;
            s2 += aggr_vec[c][2] * w;
        }
        v_inter[o][0] = s0; v_inter[o][1] = s1; v_inter[o][2] = s2;
        v_norm[o] = sqrtf(s0 * s0 + s1 * s1 + s2 * s2);
    }

    float osca[16];
#pragma unroll
    for (int o = 0; o < 16; o++) {
        float s = 0.0f;
#pragma unroll
        for (int c = 0; c < 16; c++) {
            s += v_norm[c] * sW[O_LS + c * 16 + o];
            s += aggr_sca[c] * sW[O_LS + (c + 16) * 16 + o];
        }
        osca[o] = s;
    }

    float gate[16];
#pragma unroll
    for (int o = 0; o < 16; o++) {
        float g = sW[O_BGATE + o];
#pragma unroll
        for (int c = 0; c < 16; c++) g += osca[c] * sW[O_GATE + c * 16 + o];
        gate[o] = 1.0f / (1.0f + __expf(-g));
    }

    float ovec[16][3];
#pragma unroll
    for (int o = 0; o < 16; o++) {
        float s0 = 0.0f, s1 = 0.0f, s2 = 0.0f;
#pragma unroll
        for (int c = 0; c < 16; c++) {
            float w = sW[O_LV2 + c * 16 + o];
            s0 += v_inter[c][0] * w;
            s1 += v_inter[c][1] * w;
            s2 += v_inter[c][2] * w;
        }
        ovec[o][0] = s0 * gate[o];
        ovec[o][1] = s1 * gate[o];
        ovec[o][2] = s2 * gate[o];
    }

    // ---- VNLeakyReLU on vectors ----
    float res[48];
#pragma unroll
    for (int o = 0; o < 16; o++) {
        float d0 = 0.0f, d1 = 0.0f, d2 = 0.0f;
#pragma unroll
        for (int c = 0; c < 16; c++) {
            float w = sW[O_DIR + c * 16 + o];
            d0 += ovec[c][0] * w;
            d1 += ovec[c][1] * w;
            d2 += ovec[c][2] * w;
        }
        float v0 = ovec[o][0], v1 = ovec[o][1], v2 = ovec[o][2];
        float dot = v0 * d0 + v1 * d1 + v2 * d2;
        float r0 = v0, r1 = v1, r2 = v2;
        if (dot < 0.0f) {
            float k = 0.8f * dot / (d0 * d0 + d1 * d1 + d2 * d2 + 1e-6f);
            r0 = v0 - k * d0;
            r1 = v1 - k * d1;
            r2 = v2 - k * d2;
        }
        res[o * 3 + 0] = r0; res[o * 3 + 1] = r1; res[o * 3 + 2] = r2;
    }

    // ---- writes (vectorized) ----
    float* out_sca = out;
    float* out_vec = out + (size_t)N * 16;

    float4* dv = (float4*)(out_vec + (size_t)n * 48);
#pragma unroll
    for (int q = 0; q < 12; q++)
        dv[q] = make_float4(res[q * 4 + 0], res[q * 4 + 1],
                            res[q * 4 + 2], res[q * 4 + 3]);

    float ssca[16];
#pragma unroll
    for (int o = 0; o < 16; o++) {
        float s = osca[o];
        ssca[o] = (s >= 0.0f) ? s : 0.01f * s;
    }
    float4* ds = (float4*)(out_sca + (size_t)n * 16);
#pragma unroll
    for (int q = 0; q < 4; q++)
        ds[q] = make_float4(ssca[q * 4 + 0], ssca[q * 4 + 1],
                            ssca[q * 4 + 2], ssca[q * 4 + 3]);
}

// ---------------------------------------------------------------------------
extern "C" void kernel_launch(void* const* d_in, const int* in_sizes, int n_in,
                              void* d_out, int out_size) {
    const float* node_sca = (const float*)d_in[0];
    const float* node_vec = (const float*)d_in[1];
    const float* edge_sca = (const float*)d_in[2];
    const float* edge_vec = (const float*)d_in[3];
    const float* gds      = (const float*)d_in[4];
    const int*   ei       = (const int*)d_in[5];   // [2,E]; row 0 = src
    const float* W_nss  = (const float*)d_in[6];
    const float* b_nss  = (const float*)d_in[7];
    const float* W_ess  = (const float*)d_in[8];
    const float* b_ess  = (const float*)d_in[9];
    const float* W_nsv  = (const float*)d_in[10];
    const float* b_nsv  = (const float*)d_in[11];
    const float* W_esv  = (const float*)d_in[12];
    const float* b_esv  = (const float*)d_in[13];
    const float* W_nvv  = (const float*)d_in[14];
    const float* W_evv  = (const float*)d_in[15];
    const float* W_lv   = (const float*)d_in[16];
    const float* W_lv2  = (const float*)d_in[17];
    const float* W_ls   = (const float*)d_in[18];
    const float* W_gate = (const float*)d_in[19];
    const float* b_gate = (const float*)d_in[20];
    const float* W_dir  = (const float*)d_in[21];

    int N = in_sizes[0] / 4;
    int E = in_sizes[4];

    int total4 = (N * ACC_W) / 4;
    zero_kernel<<<(total4 + 255) / 256, 256>>>(total4);

    int eblocks = (E + 255) / 256;
    edge_kernel<<<eblocks, 256>>>(edge_sca, edge_vec, gds, ei, E);

    int nblocks = (N + 127) / 128;
    node_kernel<<<nblocks, 128>>>(node_sca, node_vec,
                                  W_nss, b_nss, W_ess, b_ess,
                                  W_nsv, b_nsv, W_esv, b_esv,
                                  W_nvv, W_evv, W_lv, W_lv2,
                                  W_ls, W_gate, b_gate, W_dir,
                                  (float*)d_out, N);
}

// round 4
// speedup vs baseline: 1.8228x; 1.3808x over previous
#include <cuda_runtime.h>
#include <math.h>

#define NMAX 100000
#define ACC_W 16   // [coeff, edge_sca*coeff (6), edge_vec*coeff (9)]
#define EPB 256    // edges per block in edge kernel

__device__ __align__(16) float g_acc[NMAX * ACC_W];   // zero-initialized at load

// ---------------------------------------------------------------------------
// Edge phase: block stages 256 edges' payload via coalesced float4 loads,
// then each thread computes coeff-weighted payload and scatters with
// 4 x red.global.add.v4.f32.
// ---------------------------------------------------------------------------
__device__ __forceinline__ void red_v4(float* p, float a, float b, float c, float d) {
    asm volatile("red.global.add.v4.f32 [%0], {%1,%2,%3,%4};"
                 :: "l"(p), "f"(a), "f"(b), "f"(c), "f"(d) : "memory");
}

__global__ void __launch_bounds__(EPB)
edge_kernel(const float* __restrict__ edge_sca,
            const float* __restrict__ edge_vec,
            const float* __restrict__ gds,
            const int*   __restrict__ src_idx,
            int E) {
    __shared__ float s_sca[EPB * 6];   // 384 float4
    __shared__ float s_vec[EPB * 9];   // 576 float4

    int blockStart = blockIdx.x * EPB;
    int tid = threadIdx.x;
    int nEdges = min(EPB, E - blockStart);

    if (nEdges == EPB) {
        // fast path: fully coalesced float4 staging (exact bounds, no overlap)
        const float4* g4s = (const float4*)(edge_sca + (size_t)blockStart * 6);
        float4* s4s = (float4*)s_sca;
#pragma unroll 2
        for (int i = tid; i < (EPB * 6) / 4; i += EPB)
            s4s[i] = g4s[i];
        const float4* g4v = (const float4*)(edge_vec + (size_t)blockStart * 9);
        float4* s4v = (float4*)s_vec;
#pragma unroll 3
        for (int i = tid; i < (EPB * 9) / 4; i += EPB)
            s4v[i] = g4v[i];
    } else {
        // tail block: scalar staging
        for (int i = tid; i < nEdges * 6; i += EPB)
            s_sca[i] = edge_sca[(size_t)blockStart * 6 + i];
        for (int i = tid; i < nEdges * 9; i += EPB)
            s_vec[i] = edge_vec[(size_t)blockStart * 9 + i];
    }
    __syncthreads();

    if (tid >= nEdges) return;
    int e = blockStart + tid;

    float dist = __ldg(gds + e);
    if (dist > 10.0f || dist < 0.0f) return;     // coeff == 0 -> no contribution
    float coeff = 0.5f * (__cosf(dist * 0.31415926535f) + 1.0f);

    int src = __ldg(src_idx + e);

    float es[6];
#pragma unroll
    for (int c = 0; c < 6; c++) es[c] = s_sca[tid * 6 + c] * coeff;
    float ev[9];
#pragma unroll
    for (int c = 0; c < 9; c++) ev[c] = s_vec[tid * 9 + c] * coeff;

    float* base = g_acc + (size_t)src * ACC_W;
    red_v4(base + 0,  coeff, es[0], es[1], es[2]);
    red_v4(base + 4,  es[3], es[4], es[5], ev[0]);
    red_v4(base + 8,  ev[1], ev[2], ev[3], ev[4]);
    red_v4(base + 12, ev[5], ev[6], ev[7], ev[8]);
}

// ---------------------------------------------------------------------------
// Node phase: projections + GVPerceptronVN + VNLeakyReLU, 1 thread / node.
// Also re-zeroes g_acc after consuming it, so the graph invariant
// (g_acc == 0 at entry of every replay) holds without a separate zero kernel.
// ---------------------------------------------------------------------------
#define O_NSS   0      // 4x16
#define O_BNSS  64     // 16
#define O_ESS   80     // 6x16
#define O_BESS  176    // 16
#define O_NSV   192    // 4x16
#define O_BNSV  256    // 16
#define O_ESV   272    // 6x16
#define O_BESV  368    // 16
#define O_NVV   384    // 3x16
#define O_EVV   432    // 3x16
#define O_LV    480    // 16x16
#define O_LV2   736    // 16x16
#define O_LS    992    // 32x16
#define O_GATE  1504   // 16x16
#define O_BGATE 1760   // 16
#define O_DIR   1776   // 16x16
#define SW_TOT  2032

__global__ void __launch_bounds__(128)
node_kernel(const float* __restrict__ node_sca,
            const float* __restrict__ node_vec,
            const float* __restrict__ W_nss, const float* __restrict__ b_nss,
            const float* __restrict__ W_ess, const float* __restrict__ b_ess,
            const float* __restrict__ W_nsv, const float* __restrict__ b_nsv,
            const float* __restrict__ W_esv, const float* __restrict__ b_esv,
            const float* __restrict__ W_nvv, const float* __restrict__ W_evv,
            const float* __restrict__ W_lv,  const float* __restrict__ W_lv2,
            const float* __restrict__ W_ls,  const float* __restrict__ W_gate,
            const float* __restrict__ b_gate,const float* __restrict__ W_dir,
            float* __restrict__ out, int N) {
    __shared__ float sW[SW_TOT];
    {
        const float* srcs[16] = {W_nss, b_nss, W_ess, b_ess, W_nsv, b_nsv,
                                 W_esv, b_esv, W_nvv, W_evv, W_lv, W_lv2,
                                 W_ls, W_gate, b_gate, W_dir};
        const int offs[17] = {O_NSS, O_BNSS, O_ESS, O_BESS, O_NSV, O_BNSV,
                              O_ESV, O_BESV, O_NVV, O_EVV, O_LV, O_LV2,
                              O_LS, O_GATE, O_BGATE, O_DIR, SW_TOT};
        for (int a = 0; a < 16; a++) {
            int cnt = offs[a + 1] - offs[a];
            for (int i = threadIdx.x; i < cnt; i += blockDim.x)
                sW[offs[a] + i] = srcs[a][i];
        }
    }
    __syncthreads();

    int n = blockIdx.x * blockDim.x + threadIdx.x;
    if (n >= N) return;

    // ---- per-node inputs + edge accumulators ----
    float ns[4];
#pragma unroll
    for (int c = 0; c < 4; c++) ns[c] = node_sca[n * 4 + c];
    float nv[3][3];
#pragma unroll
    for (int c = 0; c < 3; c++)
#pragma unroll
        for (int i = 0; i < 3; i++) nv[c][i] = node_vec[n * 9 + c * 3 + i];

    float acc[16];
    {
        float4* a4 = (float4*)(g_acc + (size_t)n * ACC_W);
#pragma unroll
        for (int q = 0; q < 4; q++) {
            float4 v = a4[q];
            acc[q * 4 + 0] = v.x; acc[q * 4 + 1] = v.y;
            acc[q * 4 + 2] = v.z; acc[q * 4 + 3] = v.w;
        }
        // reset for next replay
        float4 z = make_float4(0.f, 0.f, 0.f, 0.f);
#pragma unroll
        for (int q = 0; q < 4; q++) a4[q] = z;
    }
    float Cs = acc[0];
    float* Es = acc + 1;                       // 6
    float (*Ev)[3] = (float(*)[3])(acc + 7);   // 3x3

    // ---- fused message aggregation (factored form) ----
    float aggr_sca[16];
    float aggr_vec[16][3];
#pragma unroll
    for (int o = 0; o < 16; o++) {
        float nss = sW[O_BNSS + o];
        float nsv = sW[O_BNSV + o];
#pragma unroll
        for (int c = 0; c < 4; c++) {
            nss += ns[c] * sW[O_NSS + c * 16 + o];
            nsv += ns[c] * sW[O_NSV + c * 16 + o];
        }
        float ess = sW[O_BESS + o] * Cs;
        float esv = sW[O_BESV + o] * Cs;
#pragma unroll
        for (int c = 0; c < 6; c++) {
            ess += Es[c] * sW[O_ESS + c * 16 + o];
            esv += Es[c] * sW[O_ESV + c * 16 + o];
        }
        aggr_sca[o] = nss * ess;
#pragma unroll
        for (int i = 0; i < 3; i++) {
            float nvv = 0.0f, evv = 0.0f;
#pragma unroll
            for (int c = 0; c < 3; c++) {
                nvv += nv[c][i] * sW[O_NVV + c * 16 + o];
                evv += Ev[c][i] * sW[O_EVV + c * 16 + o];
            }
            aggr_vec[o][i] = nvv * esv + nsv * evv;
        }
    }

    // ---- GVLinear ----
    float v_inter[16][3];
    float v_norm[16];
#pragma unroll
    for (int o = 0; o < 16; o++) {
        float s0 = 0.0f, s1 = 0.0f, s2 = 0.0f;
#pragma unroll
        for (int c = 0; c < 16; c++) {
            float w = sW[O_LV + c * 16 + o];
            s0 += aggr_vec[c][0] * w;
            s1 += aggr_vec[c][1] * w;
            s2 += aggr_vec[c][2] * w;
        }
        v_inter[o][0] = s0; v_inter[o][1] = s1; v_inter[o][2] = s2;
        v_norm[o] = sqrtf(s0 * s0 + s1 * s1 + s2 * s2);
    }

    float osca[16];
#pragma unroll
    for (int o = 0; o < 16; o++) {
        float s = 0.0f;
#pragma unroll
        for (int c = 0; c < 16; c++) {
            s += v_norm[c] * sW[O_LS + c * 16 + o];
            s += aggr_sca[c] * sW[O_LS + (c + 16) * 16 + o];
        }
        osca[o] = s;
    }

    float gate[16];
#pragma unroll
    for (int o = 0; o < 16; o++) {
        float g = sW[O_BGATE + o];
#pragma unroll
        for (int c = 0; c < 16; c++) g += osca[c] * sW[O_GATE + c * 16 + o];
        gate[o] = 1.0f / (1.0f + __expf(-g));
    }

    float ovec[16][3];
#pragma unroll
    for (int o = 0; o < 16; o++) {
        float s0 = 0.0f, s1 = 0.0f, s2 = 0.0f;
#pragma unroll
        for (int c = 0; c < 16; c++) {
            float w = sW[O_LV2 + c * 16 + o];
            s0 += v_inter[c][0] * w;
            s1 += v_inter[c][1] * w;
            s2 += v_inter[c][2] * w;
        }
        ovec[o][0] = s0 * gate[o];
        ovec[o][1] = s1 * gate[o];
        ovec[o][2] = s2 * gate[o];
    }

    // ---- VNLeakyReLU on vectors ----
    float res[48];
#pragma unroll
    for (int o = 0; o < 16; o++) {
        float d0 = 0.0f, d1 = 0.0f, d2 = 0.0f;
#pragma unroll
        for (int c = 0; c < 16; c++) {
            float w = sW[O_DIR + c * 16 + o];
            d0 += ovec[c][0] * w;
            d1 += ovec[c][1] * w;
            d2 += ovec[c][2] * w;
        }
        float v0 = ovec[o][0], v1 = ovec[o][1], v2 = ovec[o][2];
        float dot = v0 * d0 + v1 * d1 + v2 * d2;
        float r0 = v0, r1 = v1, r2 = v2;
        if (dot < 0.0f) {
            float k = 0.8f * dot / (d0 * d0 + d1 * d1 + d2 * d2 + 1e-6f);
            r0 = v0 - k * d0;
            r1 = v1 - k * d1;
            r2 = v2 - k * d2;
        }
        res[o * 3 + 0] = r0; res[o * 3 + 1] = r1; res[o * 3 + 2] = r2;
    }

    // ---- writes (vectorized) ----
    float* out_sca = out;
    float* out_vec = out + (size_t)N * 16;

    float4* dv = (float4*)(out_vec + (size_t)n * 48);
#pragma unroll
    for (int q = 0; q < 12; q++)
        dv[q] = make_float4(res[q * 4 + 0], res[q * 4 + 1],
                            res[q * 4 + 2], res[q * 4 + 3]);

    float ssca[16];
#pragma unroll
    for (int o = 0; o < 16; o++) {
        float s = osca[o];
        ssca[o] = (s >= 0.0f) ? s : 0.01f * s;
    }
    float4* ds = (float4*)(out_sca + (size_t)n * 16);
#pragma unroll
    for (int q = 0; q < 4; q++)
        ds[q] = make_float4(ssca[q * 4 + 0], ssca[q * 4 + 1],
                            ssca[q * 4 + 2], ssca[q * 4 + 3]);
}

// ---------------------------------------------------------------------------
extern "C" void kernel_launch(void* const* d_in, const int* in_sizes, int n_in,
                              void* d_out, int out_size) {
    const float* node_sca = (const float*)d_in[0];
    const float* node_vec = (const float*)d_in[1];
    const float* edge_sca = (const float*)d_in[2];
    const float* edge_vec = (const float*)d_in[3];
    const float* gds      = (const float*)d_in[4];
    const int*   ei       = (const int*)d_in[5];   // [2,E]; row 0 = src
    const float* W_nss  = (const float*)d_in[6];
    const float* b_nss  = (const float*)d_in[7];
    const float* W_ess  = (const float*)d_in[8];
    const float* b_ess  = (const float*)d_in[9];
    const float* W_nsv  = (const float*)d_in[10];
    const float* b_nsv  = (const float*)d_in[11];
    const float* W_esv  = (const float*)d_in[12];
    const float* b_esv  = (const float*)d_in[13];
    const float* W_nvv  = (const float*)d_in[14];
    const float* W_evv  = (const float*)d_in[15];
    const float* W_lv   = (const float*)d_in[16];
    const float* W_lv2  = (const float*)d_in[17];
    const float* W_ls   = (const float*)d_in[18];
    const float* W_gate = (const float*)d_in[19];
    const float* b_gate = (const float*)d_in[20];
    const float* W_dir  = (const float*)d_in[21];

    int N = in_sizes[0] / 4;
    int E = in_sizes[4];

    int eblocks = (E + EPB - 1) / EPB;
    edge_kernel<<<eblocks, EPB>>>(edge_sca, edge_vec, gds, ei, E);

    int nblocks = (N + 127) / 128;
    node_kernel<<<nblocks, 128>>>(node_sca, node_vec,
                                  W_nss, b_nss, W_ess, b_ess,
                                  W_nsv, b_nsv, W_esv, b_esv,
                                  W_nvv, W_evv, W_lv, W_lv2,
                                  W_ls, W_gate, b_gate, W_dir,
                                  (float*)d_out, N);
}

// round 5
// speedup vs baseline: 1.8798x; 1.0312x over previous
#include <cuda_runtime.h>
#include <math.h>

#define NMAX 100000
#define ACC_W 16   // [coeff, edge_sca*coeff (6), edge_vec*coeff (9)]
#define EPB 256    // edges per block in edge kernel

__device__ __align__(16) float g_acc[NMAX * ACC_W];   // zero-initialized at load

// ---------------------------------------------------------------------------
// Edge phase: block stages 256 edges' payload via coalesced float4 loads,
// then each thread computes coeff-weighted payload and scatters with
// 4 x red.global.add.v4.f32.
// ---------------------------------------------------------------------------
__device__ __forceinline__ void red_v4(float* p, float a, float b, float c, float d) {
    asm volatile("red.global.add.v4.f32 [%0], {%1,%2,%3,%4};"
                 :: "l"(p), "f"(a), "f"(b), "f"(c), "f"(d) : "memory");
}

__global__ void __launch_bounds__(EPB)
edge_kernel(const float* __restrict__ edge_sca,
            const float* __restrict__ edge_vec,
            const float* __restrict__ gds,
            const int*   __restrict__ src_idx,
            int E) {
    __shared__ float s_sca[EPB * 6];
    __shared__ float s_vec[EPB * 9];

    int blockStart = blockIdx.x * EPB;
    int tid = threadIdx.x;
    int nEdges = min(EPB, E - blockStart);

    if (nEdges == EPB) {
        const float4* g4s = (const float4*)(edge_sca + (size_t)blockStart * 6);
        float4* s4s = (float4*)s_sca;
#pragma unroll 2
        for (int i = tid; i < (EPB * 6) / 4; i += EPB)
            s4s[i] = g4s[i];
        const float4* g4v = (const float4*)(edge_vec + (size_t)blockStart * 9);
        float4* s4v = (float4*)s_vec;
#pragma unroll 3
        for (int i = tid; i < (EPB * 9) / 4; i += EPB)
            s4v[i] = g4v[i];
    } else {
        for (int i = tid; i < nEdges * 6; i += EPB)
            s_sca[i] = edge_sca[(size_t)blockStart * 6 + i];
        for (int i = tid; i < nEdges * 9; i += EPB)
            s_vec[i] = edge_vec[(size_t)blockStart * 9 + i];
    }
    __syncthreads();

    if (tid >= nEdges) return;
    int e = blockStart + tid;

    float dist = __ldg(gds + e);
    if (dist > 10.0f || dist < 0.0f) return;
    float coeff = 0.5f * (__cosf(dist * 0.31415926535f) + 1.0f);

    int src = __ldg(src_idx + e);

    float es[6];
#pragma unroll
    for (int c = 0; c < 6; c++) es[c] = s_sca[tid * 6 + c] * coeff;
    float ev[9];
#pragma unroll
    for (int c = 0; c < 9; c++) ev[c] = s_vec[tid * 9 + c] * coeff;

    float* base = g_acc + (size_t)src * ACC_W;
    red_v4(base + 0,  coeff, es[0], es[1], es[2]);
    red_v4(base + 4,  es[3], es[4], es[5], ev[0]);
    red_v4(base + 8,  ev[1], ev[2], ev[3], ev[4]);
    red_v4(base + 12, ev[5], ev[6], ev[7], ev[8]);
}

// ---------------------------------------------------------------------------
// Node phase, restructured for low register pressure:
//  - channel-fused aggregation->lv loop (aggr_vec never materialized)
//  - v_inter parked in padded SMEM across the scalar path
//  - node_vec staged via coalesced SMEM
// Re-zeroes g_acc after consuming it (keeps graph replay invariant).
// ---------------------------------------------------------------------------
#define O_NSS   0      // 4x16
#define O_BNSS  64     // 16
#define O_ESS   80     // 6x16
#define O_BESS  176    // 16
#define O_NSV   192    // 4x16
#define O_BNSV  256    // 16
#define O_ESV   272    // 6x16
#define O_BESV  368    // 16
#define O_NVV   384    // 3x16
#define O_EVV   432    // 3x16
#define O_LV    480    // 16x16
#define O_LV2   736    // 16x16
#define O_LS    992    // 32x16
#define O_GATE  1504   // 16x16
#define O_BGATE 1760   // 16
#define O_DIR   1776   // 16x16
#define SW_TOT  2032

#define NPB 128        // nodes per block
#define VI_STRIDE 49   // 48 + 1 pad -> odd stride, conflict-free

__global__ void __launch_bounds__(NPB)
node_kernel(const float* __restrict__ node_sca,
            const float* __restrict__ node_vec,
            const float* __restrict__ W_nss, const float* __restrict__ b_nss,
            const float* __restrict__ W_ess, const float* __restrict__ b_ess,
            const float* __restrict__ W_nsv, const float* __restrict__ b_nsv,
            const float* __restrict__ W_esv, const float* __restrict__ b_esv,
            const float* __restrict__ W_nvv, const float* __restrict__ W_evv,
            const float* __restrict__ W_lv,  const float* __restrict__ W_lv2,
            const float* __restrict__ W_ls,  const float* __restrict__ W_gate,
            const float* __restrict__ b_gate,const float* __restrict__ W_dir,
            float* __restrict__ out, int N) {
    __shared__ float sW[SW_TOT];
    __shared__ float s_vi[NPB * VI_STRIDE];   // per-thread v_inter parking
    __shared__ float s_nv[NPB * 9];           // staged node_vec

    int tid = threadIdx.x;
    int blockStart = blockIdx.x * NPB;
    int nNodes = min(NPB, N - blockStart);

    {   // weights -> shared
        const float* srcs[16] = {W_nss, b_nss, W_ess, b_ess, W_nsv, b_nsv,
                                 W_esv, b_esv, W_nvv, W_evv, W_lv, W_lv2,
                                 W_ls, W_gate, b_gate, W_dir};
        const int offs[17] = {O_NSS, O_BNSS, O_ESS, O_BESS, O_NSV, O_BNSV,
                              O_ESV, O_BESV, O_NVV, O_EVV, O_LV, O_LV2,
                              O_LS, O_GATE, O_BGATE, O_DIR, SW_TOT};
        for (int a = 0; a < 16; a++) {
            int cnt = offs[a + 1] - offs[a];
            for (int i = tid; i < cnt; i += NPB)
                sW[offs[a] + i] = srcs[a][i];
        }
    }
    {   // node_vec -> shared (coalesced)
        if (nNodes == NPB) {
            const float4* g4 = (const float4*)(node_vec + (size_t)blockStart * 9);
            float4* s4 = (float4*)s_nv;
#pragma unroll 3
            for (int i = tid; i < (NPB * 9) / 4; i += NPB)
                s4[i] = g4[i];
        } else {
            for (int i = tid; i < nNodes * 9; i += NPB)
                s_nv[i] = node_vec[(size_t)blockStart * 9 + i];
        }
    }
    __syncthreads();

    if (tid >= nNodes) return;
    int n = blockStart + tid;

    // ---- per-node inputs ----
    float4 ns4 = ((const float4*)node_sca)[n];
    float ns[4] = {ns4.x, ns4.y, ns4.z, ns4.w};
    float nv[3][3];
#pragma unroll
    for (int c = 0; c < 3; c++)
#pragma unroll
        for (int i = 0; i < 3; i++) nv[c][i] = s_nv[tid * 9 + c * 3 + i];

    float acc[16];
    {
        float4* a4 = (float4*)(g_acc + (size_t)n * ACC_W);
#pragma unroll
        for (int q = 0; q < 4; q++) {
            float4 v = a4[q];
            acc[q * 4 + 0] = v.x; acc[q * 4 + 1] = v.y;
            acc[q * 4 + 2] = v.z; acc[q * 4 + 3] = v.w;
        }
        float4 z = make_float4(0.f, 0.f, 0.f, 0.f);
#pragma unroll
        for (int q = 0; q < 4; q++) a4[q] = z;   // reset for next replay
    }
    float Cs = acc[0];
    float* Es = acc + 1;                       // [6]
    float (*Ev)[3] = (float(*)[3])(acc + 7);   // [3][3]

    // ---- fused: per channel c compute aggr_{sca,vec}[c], accumulate into
    //      v_inter (lv) and the aggr_sca part of osca (ls second half) ----
    float v_inter[16][3];
    float osca_s[16];
#pragma unroll
    for (int o = 0; o < 16; o++) {
        v_inter[o][0] = 0.f; v_inter[o][1] = 0.f; v_inter[o][2] = 0.f;
        osca_s[o] = 0.f;
    }

#pragma unroll
    for (int c = 0; c < 16; c++) {
        float nss = sW[O_BNSS + c];
        float nsv = sW[O_BNSV + c];
#pragma unroll
        for (int k = 0; k < 4; k++) {
            nss += ns[k] * sW[O_NSS + k * 16 + c];
            nsv += ns[k] * sW[O_NSV + k * 16 + c];
        }
        float ess = sW[O_BESS + c] * Cs;
        float esv = sW[O_BESV + c] * Cs;
#pragma unroll
        for (int k = 0; k < 6; k++) {
            ess += Es[k] * sW[O_ESS + k * 16 + c];
            esv += Es[k] * sW[O_ESV + k * 16 + c];
        }
        float a_sca = nss * ess;                 // aggr_sca[c]
        float av[3];
#pragma unroll
        for (int i = 0; i < 3; i++) {
            float nvv = 0.f, evv = 0.f;
#pragma unroll
            for (int k = 0; k < 3; k++) {
                nvv += nv[k][i] * sW[O_NVV + k * 16 + c];
                evv += Ev[k][i] * sW[O_EVV + k * 16 + c];
            }
            av[i] = nvv * esv + nsv * evv;       // aggr_vec[c][i]
        }
        // spread into lv accumulation + ls scalar half
#pragma unroll
        for (int o = 0; o < 16; o++) {
            float wlv = sW[O_LV + c * 16 + o];
            v_inter[o][0] += av[0] * wlv;
            v_inter[o][1] += av[1] * wlv;
            v_inter[o][2] += av[2] * wlv;
            osca_s[o] += a_sca * sW[O_LS + (c + 16) * 16 + o];
        }
    }

    // ---- v_norm; park v_inter in SMEM, freeing its registers ----
    float v_norm[16];
#pragma unroll
    for (int o = 0; o < 16; o++) {
        v_norm[o] = sqrtf(v_inter[o][0] * v_inter[o][0] +
                          v_inter[o][1] * v_inter[o][1] +
                          v_inter[o][2] * v_inter[o][2]);
        s_vi[tid * VI_STRIDE + o * 3 + 0] = v_inter[o][0];
        s_vi[tid * VI_STRIDE + o * 3 + 1] = v_inter[o][1];
        s_vi[tid * VI_STRIDE + o * 3 + 2] = v_inter[o][2];
    }

    // ---- scalar path: osca, gate ----
    float osca[16];
#pragma unroll
    for (int o = 0; o < 16; o++) {
        float s = osca_s[o];
#pragma unroll
        for (int c = 0; c < 16; c++)
            s += v_norm[c] * sW[O_LS + c * 16 + o];
        osca[o] = s;
    }

    float gate[16];
#pragma unroll
    for (int o = 0; o < 16; o++) {
        float g = sW[O_BGATE + o];
#pragma unroll
        for (int c = 0; c < 16; c++) g += osca[c] * sW[O_GATE + c * 16 + o];
        gate[o] = 1.0f / (1.0f + __expf(-g));
    }

    // ---- lv2: ovec from SMEM-parked v_inter ----
    float ovec[16][3];
#pragma unroll
    for (int o = 0; o < 16; o++) {
        ovec[o][0] = 0.f; ovec[o][1] = 0.f; ovec[o][2] = 0.f;
    }
#pragma unroll
    for (int c = 0; c < 16; c++) {
        float vi0 = s_vi[tid * VI_STRIDE + c * 3 + 0];
        float vi1 = s_vi[tid * VI_STRIDE + c * 3 + 1];
        float vi2 = s_vi[tid * VI_STRIDE + c * 3 + 2];
#pragma unroll
        for (int o = 0; o < 16; o++) {
            float w = sW[O_LV2 + c * 16 + o];
            ovec[o][0] += vi0 * w;
            ovec[o][1] += vi1 * w;
            ovec[o][2] += vi2 * w;
        }
    }
#pragma unroll
    for (int o = 0; o < 16; o++) {
        ovec[o][0] *= gate[o];
        ovec[o][1] *= gate[o];
        ovec[o][2] *= gate[o];
    }

    // ---- VNLeakyReLU + writes ----
    float res[48];
#pragma unroll
    for (int o = 0; o < 16; o++) {
        float d0 = 0.f, d1 = 0.f, d2 = 0.f;
#pragma unroll
        for (int c = 0; c < 16; c++) {
            float w = sW[O_DIR + c * 16 + o];
            d0 += ovec[c][0] * w;
            d1 += ovec[c][1] * w;
            d2 += ovec[c][2] * w;
        }
        float v0 = ovec[o][0], v1 = ovec[o][1], v2 = ovec[o][2];
        float dot = v0 * d0 + v1 * d1 + v2 * d2;
        float r0 = v0, r1 = v1, r2 = v2;
        if (dot < 0.0f) {
            float k = 0.8f * dot / (d0 * d0 + d1 * d1 + d2 * d2 + 1e-6f);
            r0 = v0 - k * d0;
            r1 = v1 - k * d1;
            r2 = v2 - k * d2;
        }
        res[o * 3 + 0] = r0; res[o * 3 + 1] = r1; res[o * 3 + 2] = r2;
    }

    float* out_sca = out;
    float* out_vec = out + (size_t)N * 16;

    float4* dv = (float4*)(out_vec + (size_t)n * 48);
#pragma unroll
    for (int q = 0; q < 12; q++)
        dv[q] = make_float4(res[q * 4 + 0], res[q * 4 + 1],
                            res[q * 4 + 2], res[q * 4 + 3]);

    float ssca[16];
#pragma unroll
    for (int o = 0; o < 16; o++) {
        float s = osca[o];
        ssca[o] = (s >= 0.0f) ? s : 0.01f * s;
    }
    float4* ds = (float4*)(out_sca + (size_t)n * 16);
#pragma unroll
    for (int q = 0; q < 4; q++)
        ds[q] = make_float4(ssca[q * 4 + 0], ssca[q * 4 + 1],
                            ssca[q * 4 + 2], ssca[q * 4 + 3]);
}

// ---------------------------------------------------------------------------
extern "C" void kernel_launch(void* const* d_in, const int* in_sizes, int n_in,
                              void* d_out, int out_size) {
    const float* node_sca = (const float*)d_in[0];
    const float* node_vec = (const float*)d_in[1];
    const float* edge_sca = (const float*)d_in[2];
    const float* edge_vec = (const float*)d_in[3];
    const float* gds      = (const float*)d_in[4];
    const int*   ei       = (const int*)d_in[5];   // [2,E]; row 0 = src
    const float* W_nss  = (const float*)d_in[6];
    const float* b_nss  = (const float*)d_in[7];
    const float* W_ess  = (const float*)d_in[8];
    const float* b_ess  = (const float*)d_in[9];
    const float* W_nsv  = (const float*)d_in[10];
    const float* b_nsv  = (const float*)d_in[11];
    const float* W_esv  = (const float*)d_in[12];
    const float* b_esv  = (const float*)d_in[13];
    const float* W_nvv  = (const float*)d_in[14];
    const float* W_evv  = (const float*)d_in[15];
    const float* W_lv   = (const float*)d_in[16];
    const float* W_lv2  = (const float*)d_in[17];
    const float* W_ls   = (const float*)d_in[18];
    const float* W_gate = (const float*)d_in[19];
    const float* b_gate = (const float*)d_in[20];
    const float* W_dir  = (const float*)d_in[21];

    int N = in_sizes[0] / 4;
    int E = in_sizes[4];

    int eblocks = (E + EPB - 1) / EPB;
    edge_kernel<<<eblocks, EPB>>>(edge_sca, edge_vec, gds, ei, E);

    int nblocks = (N + NPB - 1) / NPB;
    node_kernel<<<nblocks, NPB>>>(node_sca, node_vec,
                                  W_nss, b_nss, W_ess, b_ess,
                                  W_nsv, b_nsv, W_esv, b_esv,
                                  W_nvv, W_evv, W_lv, W_lv2,
                                  W_ls, W_gate, b_gate, W_dir,
                                  (float*)d_out, N);
}